// round 1
// baseline (speedup 1.0000x reference)
#include <cuda_runtime.h>
#include <math.h>

#define SEQ   2048
#define BATCH 2
#define NTOK  (SEQ*BATCH)      // 4096
#define HID   896
#define NH    14
#define NKV   2
#define HD    64
#define NGRP  (NH/NKV)         // 7

// ---------------- scratch (allocation-free rule: __device__ globals) --------
__device__ float g_q  [NTOK*NH *HD];   // 14.7 MB
__device__ float g_k  [NTOK*NKV*HD];   //  2.1 MB
__device__ float g_v  [NTOK*NKV*HD];   //  2.1 MB
__device__ float g_att[NTOK*NH *HD];   // 14.7 MB
__device__ float g_zero[HID];          // zero-initialized, never written

// ---------------- generic GEMM: C[M,N] = A[M,K] @ W[K,N] + bias[N] ----------
// 64x64 block tile, BK=16, 256 threads, 4x4 microtile per thread.
__global__ void gemm_bias_kernel(const float* __restrict__ A,
                                 const float* __restrict__ W,
                                 const float* __restrict__ bias,
                                 float* __restrict__ C,
                                 int M, int N, int K) {
    __shared__ float As[16*68];   // [kk][m], pitch 68 keeps float4 reads aligned
    __shared__ float Ws[16*64];   // [kk][n]
    const int tid = threadIdx.x;
    const int tx = tid & 15, ty = tid >> 4;
    const int rowBase = blockIdx.y * 64;
    const int colBase = blockIdx.x * 64;

    float acc[4][4];
#pragma unroll
    for (int i = 0; i < 4; i++)
#pragma unroll
        for (int j = 0; j < 4; j++) acc[i][j] = 0.f;

    for (int k0 = 0; k0 < K; k0 += 16) {
#pragma unroll
        for (int p = 0; p < 4; p++) {             // 64x16 A tile
            int i = tid + p * 256;
            int m = i >> 4, kk = i & 15;
            As[kk*68 + m] = A[(rowBase + m) * K + k0 + kk];
        }
#pragma unroll
        for (int p = 0; p < 4; p++) {             // 16x64 W tile
            int i = tid + p * 256;
            int kk = i >> 6, n = i & 63;
            Ws[kk*64 + n] = W[(k0 + kk) * N + colBase + n];
        }
        __syncthreads();
#pragma unroll
        for (int kk = 0; kk < 16; kk++) {
            float4 a4 = *(const float4*)&As[kk*68 + ty*4];
            float4 b4 = *(const float4*)&Ws[kk*64 + tx*4];
            float a[4] = {a4.x, a4.y, a4.z, a4.w};
            float b[4] = {b4.x, b4.y, b4.z, b4.w};
#pragma unroll
            for (int i = 0; i < 4; i++)
#pragma unroll
                for (int j = 0; j < 4; j++) acc[i][j] += a[i] * b[j];
        }
        __syncthreads();
    }
#pragma unroll
    for (int i = 0; i < 4; i++) {
        int m = rowBase + ty*4 + i;
#pragma unroll
        for (int j = 0; j < 4; j++) {
            int n = colBase + tx*4 + j;
            C[m * N + n] = acc[i][j] + bias[n];
        }
    }
}

// ---------------- RoPE (in-place on q and k) --------------------------------
// One thread handles the (d, d+32) rotation pair of one (token, head).
__global__ void rope_kernel(float* __restrict__ q, float* __restrict__ k) {
    const int nq = NTOK * NH * 32;
    const int nk = NTOK * NKV * 32;
    int idx = blockIdx.x * blockDim.x + threadIdx.x;
    if (idx >= nq + nk) return;

    float* buf; int tok, off, d;
    if (idx < nq) {
        d = idx & 31;
        int r = idx >> 5;
        int h = r % NH; tok = r / NH;
        buf = q; off = tok * NH * HD + h * HD;
    } else {
        int r2 = idx - nq;
        d = r2 & 31;
        int r = r2 >> 5;
        int h = r & 1; tok = r >> 1;
        buf = k; off = tok * NKV * HD + h * HD;
    }
    int s = tok & (SEQ - 1);                 // position within sequence
    float inv = powf(1.0e6f, -((float)d) * (1.0f / 32.0f));  // theta^(-2d/64)
    float ang = (float)s * inv;
    float c = cosf(ang), sn = sinf(ang);
    float x1 = buf[off + d];
    float x2 = buf[off + d + 32];
    buf[off + d]      = x1 * c - x2 * sn;
    buf[off + d + 32] = x2 * c + x1 * sn;
}

// ---------------- flash attention: 64q x 64k tiles, causal ------------------
// grid = (32 q-tiles, 28 bh), 256 threads. Online softmax, stats in registers
// replicated across the 16 lanes that own a row (width-16 shfl reductions).
__global__ void attn_kernel(const float* __restrict__ Q,
                            const float* __restrict__ K,
                            const float* __restrict__ V,
                            float* __restrict__ O) {
    extern __shared__ float sm[];
    float* Qt = sm;                 // [d][q]  pitch 68
    float* Kt = sm + 64*68;         // [d][j]  pitch 68
    float* Ps = sm + 2*64*68;       // [q][j]  pitch 68
    float* Vs = sm + 3*64*68;       // [j][d]  pitch 64

    const int qt  = blockIdx.x;
    const int bh  = blockIdx.y;
    const int b   = bh / NH, h = bh % NH, kvh = h / NGRP;
    const int tid = threadIdx.x;
    const int tx  = tid & 15, ty = tid >> 4;
    const int tokQ = b * SEQ + qt * 64;

    // load Q tile transposed, fold 1/sqrt(64) into Q
    for (int i = tid; i < 64*64; i += 256) {
        int q = i >> 6, d = i & 63;
        Qt[d*68 + q] = Q[(tokQ + q) * (NH*HD) + h*HD + d] * 0.125f;
    }

    float m_i[4], l_i[4], acc[4][4];
#pragma unroll
    for (int i = 0; i < 4; i++) {
        m_i[i] = -1e30f; l_i[i] = 0.f;
#pragma unroll
        for (int j = 0; j < 4; j++) acc[i][j] = 0.f;
    }
    __syncthreads();

    for (int kt = 0; kt <= qt; kt++) {
        const int tokK = b * SEQ + kt * 64;
        for (int i = tid; i < 64*64; i += 256) {
            int j = i >> 6, d = i & 63;
            Kt[d*68 + j] = K[(tokK + j) * (NKV*HD) + kvh*HD + d];
            Vs[j*64 + d] = V[(tokK + j) * (NKV*HD) + kvh*HD + d];
        }
        __syncthreads();

        // S = (Q/8) @ K^T  (64x64, inner dim d)
        float s[4][4];
#pragma unroll
        for (int i = 0; i < 4; i++)
#pragma unroll
            for (int j = 0; j < 4; j++) s[i][j] = 0.f;
#pragma unroll 8
        for (int d = 0; d < 64; d++) {
            float4 a4 = *(const float4*)&Qt[d*68 + ty*4];
            float4 b4 = *(const float4*)&Kt[d*68 + tx*4];
            float a[4]  = {a4.x, a4.y, a4.z, a4.w};
            float bb[4] = {b4.x, b4.y, b4.z, b4.w};
#pragma unroll
            for (int i = 0; i < 4; i++)
#pragma unroll
                for (int j = 0; j < 4; j++) s[i][j] += a[i] * bb[j];
        }

        if (kt == qt) {  // causal mask only needed on the diagonal tile
#pragma unroll
            for (int i = 0; i < 4; i++)
#pragma unroll
                for (int j = 0; j < 4; j++)
                    if (tx*4 + j > ty*4 + i) s[i][j] = -1e30f;
        }

        // online softmax update (per row; 16 lanes share a row)
#pragma unroll
        for (int i = 0; i < 4; i++) {
            float tmax = fmaxf(fmaxf(s[i][0], s[i][1]), fmaxf(s[i][2], s[i][3]));
#pragma unroll
            for (int o = 8; o > 0; o >>= 1)
                tmax = fmaxf(tmax, __shfl_xor_sync(0xffffffffu, tmax, o, 16));
            float newm  = fmaxf(m_i[i], tmax);
            float alpha = __expf(m_i[i] - newm);
            m_i[i] = newm;
            float rsum = 0.f;
#pragma unroll
            for (int j = 0; j < 4; j++) {
                float p = __expf(s[i][j] - newm);
                s[i][j] = p; rsum += p;
            }
#pragma unroll
            for (int o = 8; o > 0; o >>= 1)
                rsum += __shfl_xor_sync(0xffffffffu, rsum, o, 16);
            l_i[i] = l_i[i] * alpha + rsum;
#pragma unroll
            for (int j = 0; j < 4; j++) acc[i][j] *= alpha;
        }

        // stage P, then O += P @ V
#pragma unroll
        for (int i = 0; i < 4; i++)
            *(float4*)&Ps[(ty*4 + i)*68 + tx*4] =
                make_float4(s[i][0], s[i][1], s[i][2], s[i][3]);
        __syncthreads();
#pragma unroll 4
        for (int kk = 0; kk < 64; kk++) {
            float4 v4 = *(const float4*)&Vs[kk*64 + tx*4];
            float vv[4] = {v4.x, v4.y, v4.z, v4.w};
            float a[4];
#pragma unroll
            for (int i = 0; i < 4; i++) a[i] = Ps[(ty*4 + i)*68 + kk];
#pragma unroll
            for (int i = 0; i < 4; i++)
#pragma unroll
                for (int j = 0; j < 4; j++) acc[i][j] += a[i] * vv[j];
        }
        __syncthreads();
    }

    // epilogue: normalize and store
#pragma unroll
    for (int i = 0; i < 4; i++) {
        float inv = 1.0f / l_i[i];
        int tok = tokQ + ty*4 + i;
#pragma unroll
        for (int j = 0; j < 4; j++)
            O[tok * (NH*HD) + h*HD + tx*4 + j] = acc[i][j] * inv;
    }
}

// ---------------- launch ----------------------------------------------------
extern "C" void kernel_launch(void* const* d_in, const int* in_sizes, int n_in,
                              void* d_out, int out_size) {
    const float* X  = (const float*)d_in[0];
    // d_in[1] = attention_mask: provably the fixed causal mask -> implemented analytically
    const float* Wq = (const float*)d_in[2];
    const float* bq = (const float*)d_in[3];
    const float* Wk = (const float*)d_in[4];
    const float* bk = (const float*)d_in[5];
    const float* Wv = (const float*)d_in[6];
    const float* bv = (const float*)d_in[7];
    const float* Wo = (const float*)d_in[8];
    float* out = (float*)d_out;

    float *q, *k, *v, *att, *zb;
    cudaGetSymbolAddress((void**)&q,   g_q);
    cudaGetSymbolAddress((void**)&k,   g_k);
    cudaGetSymbolAddress((void**)&v,   g_v);
    cudaGetSymbolAddress((void**)&att, g_att);
    cudaGetSymbolAddress((void**)&zb,  g_zero);

    const dim3 blk(256);

    // QKV projections
    gemm_bias_kernel<<<dim3(NH*HD/64,  NTOK/64), blk>>>(X, Wq, bq, q, NTOK, NH*HD,  HID);
    gemm_bias_kernel<<<dim3(NKV*HD/64, NTOK/64), blk>>>(X, Wk, bk, k, NTOK, NKV*HD, HID);
    gemm_bias_kernel<<<dim3(NKV*HD/64, NTOK/64), blk>>>(X, Wv, bv, v, NTOK, NKV*HD, HID);

    // RoPE
    int nrope = NTOK*NH*32 + NTOK*NKV*32;
    rope_kernel<<<(nrope + 255) / 256, 256>>>(q, k);

    // attention
    const int smem = (3*64*68 + 64*64) * (int)sizeof(float);  // 68608 B
    cudaFuncSetAttribute(attn_kernel, cudaFuncAttributeMaxDynamicSharedMemorySize, smem);
    attn_kernel<<<dim3(SEQ/64, BATCH*NH), blk, smem>>>(q, k, v, att);

    // output projection
    gemm_bias_kernel<<<dim3(HID/64, NTOK/64), blk>>>(att, Wo, zb, out, NTOK, HID, HID);
}

// round 4
// speedup vs baseline: 2.6392x; 2.6392x over previous
#include <cuda_runtime.h>
#include <math.h>
#include <stdint.h>

#define SEQ   2048
#define BATCH 2
#define NTOK  (SEQ*BATCH)      // 4096
#define HID   896
#define NH    14
#define NKV   2
#define HD    64
#define NGRP  (NH/NKV)         // 7
#define KDIM  896
#define KITERS (KDIM/16)       // 56

// ---------------- scratch (allocation-free rule: __device__ globals) --------
__device__ float g_q  [NTOK*NH *HD];
__device__ float g_k  [NTOK*NKV*HD];
__device__ float g_v  [NTOK*NKV*HD];
__device__ float g_att[NTOK*NH *HD];
__device__ float g_xr [NTOK*HID];      // X rounded to tf32
__device__ float g_wq [HID*NH*HD];     // rounded weight copies (same layout [K,N])
__device__ float g_wk [HID*NKV*HD];
__device__ float g_wv [HID*NKV*HD];
__device__ float g_wo [HID*HID];
__device__ float g_zero[HID];          // zero-initialized, never written

// ---------------- helpers ---------------------------------------------------
__device__ __forceinline__ uint32_t cvta_smem(const void* p) {
    uint32_t a;
    asm("{ .reg .u64 t; cvta.to.shared.u64 t, %1; cvt.u32.u64 %0, t; }"
        : "=r"(a) : "l"(p));
    return a;
}
__device__ __forceinline__ float rn_tf32(float x) {
    uint32_t b;
    asm("cvt.rna.tf32.f32 %0, %1;" : "=r"(b) : "f"(x));
    return __uint_as_float(b);
}
__device__ __forceinline__ uint32_t fb(float x) { return __float_as_uint(x); }

// D += A(16x8) * B(8x8), tf32 operands, f32 accum
__device__ __forceinline__ void mma8(float* c, const uint32_t* a, const uint32_t* b) {
    asm volatile("mma.sync.aligned.m16n8k8.row.col.f32.tf32.tf32.f32 "
        "{%0,%1,%2,%3}, {%4,%5,%6,%7}, {%8,%9}, {%0,%1,%2,%3};"
        : "+f"(c[0]), "+f"(c[1]), "+f"(c[2]), "+f"(c[3])
        : "r"(a[0]), "r"(a[1]), "r"(a[2]), "r"(a[3]), "r"(b[0]), "r"(b[1]));
}

// ---------------- prep kernels ----------------------------------------------
__global__ void copy_rn_kernel(const float* __restrict__ src, float* __restrict__ dst, int n) {
    int i = blockIdx.x * blockDim.x + threadIdx.x;
    if (i < n) dst[i] = rn_tf32(src[i]);
}

// ---------------- tf32 mma GEMM body ----------------------------------------
// C[M,N] = A[M,KDIM] @ W[KDIM,N] + bias, CTA tile 128 x 128, 256 thr / 8 warps.
// warp tile 32x64. BK=16, double-buffered cp.async. A,W pre-rounded to tf32.
__device__ __forceinline__ void gemm_body(
    const float* __restrict__ A, const float* __restrict__ W,
    const float* __restrict__ bias, float* __restrict__ C,
    int N, int colBase, int rnd)
{
    __shared__ float As[2][128*20];
    __shared__ float Bs[2][16*132];

    const int tid  = threadIdx.x;
    const int lane = tid & 31, wid = tid >> 5;
    const int wrow = (wid >> 1) * 32, wcol = (wid & 1) * 64;
    const int rowBase = blockIdx.y * 128;

    uint32_t sA[2] = { cvta_smem(As[0]), cvta_smem(As[1]) };
    uint32_t sB[2] = { cvta_smem(Bs[0]), cvta_smem(Bs[1]) };

    auto load = [&](int it) {
        int buf = it & 1, k0 = it * 16;
#pragma unroll
        for (int p = 0; p < 2; p++) {                    // A: 128x16
            int id = tid + p * 256;
            int row = id >> 2, c4 = (id & 3) << 2;
            const float* src = A + (size_t)(rowBase + row) * KDIM + k0 + c4;
            uint32_t dst = sA[buf] + (row * 20 + c4) * 4;
            asm volatile("cp.async.cg.shared.global [%0], [%1], 16;" :: "r"(dst), "l"(src));
        }
#pragma unroll
        for (int p = 0; p < 2; p++) {                    // B: 16x128
            int id = tid + p * 256;
            int kr = id >> 5, c4 = (id & 31) << 2;
            const float* src = W + (size_t)(k0 + kr) * N + colBase + c4;
            uint32_t dst = sB[buf] + (kr * 132 + c4) * 4;
            asm volatile("cp.async.cg.shared.global [%0], [%1], 16;" :: "r"(dst), "l"(src));
        }
        asm volatile("cp.async.commit_group;" ::: "memory");
    };

    float acc[2][8][4];
#pragma unroll
    for (int mi = 0; mi < 2; mi++)
#pragma unroll
        for (int ni = 0; ni < 8; ni++)
#pragma unroll
            for (int t = 0; t < 4; t++) acc[mi][ni][t] = 0.f;

    load(0); load(1);

    for (int it = 0; it < KITERS; it++) {
        int buf = it & 1;
        if (it < KITERS - 1) asm volatile("cp.async.wait_group 1;" ::: "memory");
        else                 asm volatile("cp.async.wait_group 0;" ::: "memory");
        __syncthreads();

        const float* as = As[buf];
        const float* bs = Bs[buf];
#pragma unroll
        for (int ks = 0; ks < 2; ks++) {
            int ko = ks * 8;
            uint32_t af[2][4];
#pragma unroll
            for (int mi = 0; mi < 2; mi++) {
                const float* qb = as + (wrow + mi*16 + (lane>>2)) * 20 + ko + (lane&3);
                af[mi][0] = fb(qb[0]);      af[mi][1] = fb(qb[8*20]);
                af[mi][2] = fb(qb[4]);      af[mi][3] = fb(qb[8*20+4]);
            }
#pragma unroll
            for (int ni = 0; ni < 8; ni++) {
                const float* bb = bs + (ko + (lane&3)) * 132 + wcol + ni*8 + (lane>>2);
                uint32_t bf[2] = { fb(bb[0]), fb(bb[4*132]) };
                mma8(acc[0][ni], af[0], bf);
                mma8(acc[1][ni], af[1], bf);
            }
        }
        __syncthreads();
        if (it + 2 < KITERS) load(it + 2);
    }

#pragma unroll
    for (int mi = 0; mi < 2; mi++) {
        int r0 = rowBase + wrow + mi*16 + (lane>>2);
#pragma unroll
        for (int ni = 0; ni < 8; ni++) {
            int c = colBase + wcol + ni*8 + 2*(lane&3);
            float v0 = acc[mi][ni][0] + bias[c];
            float v1 = acc[mi][ni][1] + bias[c+1];
            float v2 = acc[mi][ni][2] + bias[c];
            float v3 = acc[mi][ni][3] + bias[c+1];
            if (rnd) { v0 = rn_tf32(v0); v1 = rn_tf32(v1); v2 = rn_tf32(v2); v3 = rn_tf32(v3); }
            float2* p0 = (float2*)&C[(size_t)r0 * N + c];
            float2* p1 = (float2*)&C[(size_t)(r0+8) * N + c];
            *p0 = make_float2(v0, v1);
            *p1 = make_float2(v2, v3);
        }
    }
}

// fused QKV: blockIdx.x 0..6 -> Wq col tiles, 7 -> Wk, 8 -> Wv (rounded output)
__global__ void __launch_bounds__(256) gemm_qkv_kernel(
    const float* __restrict__ X,
    const float* __restrict__ wq, const float* __restrict__ wk, const float* __restrict__ wv,
    const float* __restrict__ bq, const float* __restrict__ bk, const float* __restrict__ bv,
    float* __restrict__ q, float* __restrict__ k, float* __restrict__ v)
{
    int bx = blockIdx.x;
    if (bx < 7)      gemm_body(X, wq, bq, q, NH*HD,  bx*128, 0);
    else if (bx == 7) gemm_body(X, wk, bk, k, NKV*HD, 0,      0);
    else              gemm_body(X, wv, bv, v, NKV*HD, 0,      1);
}

__global__ void __launch_bounds__(256) gemm_o_kernel(
    const float* __restrict__ A, const float* __restrict__ W,
    const float* __restrict__ bias, float* __restrict__ C)
{
    gemm_body(A, W, bias, C, HID, blockIdx.x * 128, 0);
}

// ---------------- RoPE (in-place, rounds output to tf32) --------------------
__global__ void rope_kernel(float* __restrict__ q, float* __restrict__ k) {
    const int nq = NTOK * NH * 32;
    const int nk = NTOK * NKV * 32;
    int idx = blockIdx.x * blockDim.x + threadIdx.x;
    if (idx >= nq + nk) return;

    float* buf; int tok, off, d;
    if (idx < nq) {
        d = idx & 31;
        int r = idx >> 5;
        int h = r % NH; tok = r / NH;
        buf = q; off = tok * NH * HD + h * HD;
    } else {
        int r2 = idx - nq;
        d = r2 & 31;
        int r = r2 >> 5;
        int h = r & 1; tok = r >> 1;
        buf = k; off = tok * NKV * HD + h * HD;
    }
    int s = tok & (SEQ - 1);
    float inv = powf(1.0e6f, -((float)d) * (1.0f / 32.0f));
    float ang = (float)s * inv;
    float c = cosf(ang), sn = sinf(ang);
    float x1 = buf[off + d];
    float x2 = buf[off + d + 32];
    buf[off + d]      = rn_tf32(x1 * c - x2 * sn);
    buf[off + d + 32] = rn_tf32(x2 * c + x1 * sn);
}

// ---------------- flash attention, tf32 mma ---------------------------------
// 64q x 64k tile, 128 threads / 4 warps; warp = 16 q-rows x all 64 cols.
// smem: Qs[64][68], Ks[2][64][68], Vs[2][64][68], Ps[64][68]  (104448 B)
#define TPITCH 68
#define TFLOAT (64*TPITCH)            // 4352 floats per tile
#define ATT_SMEM (6*TFLOAT*4)         // 104448 bytes

__global__ void __launch_bounds__(128) attn_kernel(
    const float* __restrict__ Q, const float* __restrict__ K,
    const float* __restrict__ V, float* __restrict__ O)
{
    extern __shared__ float sm[];
    float* Qs = sm;                     // [q][d]
    float* Ps = sm + 5*TFLOAT;          // [q][j]
    uint32_t smb = cvta_smem(sm);

    const int qt  = blockIdx.x;
    const int bh  = blockIdx.y;
    const int b   = bh / NH, h = bh % NH, kvh = h / NGRP;
    const int tid = threadIdx.x;
    const int lane = tid & 31, wid = tid >> 5;
    const int tokQ = b * SEQ + qt * 64;
    const int rloc = wid * 16 + (lane >> 2);     // local q row (first of pair)

    // Q tile: 64 rows x 16 float4
    {
#pragma unroll
        for (int p = 0; p < 8; p++) {
            int id = tid + p * 128;
            int row = id >> 4, c4 = (id & 15) << 2;
            const float* src = Q + (size_t)(tokQ + row) * (NH*HD) + h*HD + c4;
            uint32_t dst = smb + (row * TPITCH + c4) * 4;
            asm volatile("cp.async.cg.shared.global [%0], [%1], 16;" :: "r"(dst), "l"(src));
        }
    }
    auto loadKV = [&](int kt) {
        int buf = kt & 1;
        int tokK = b * SEQ + kt * 64;
        uint32_t kdst = smb + (1 + buf) * TFLOAT * 4;
        uint32_t vdst = smb + (3 + buf) * TFLOAT * 4;
#pragma unroll
        for (int p = 0; p < 8; p++) {
            int id = tid + p * 128;
            int row = id >> 4, c4 = (id & 15) << 2;
            const float* ksrc = K + (size_t)(tokK + row) * (NKV*HD) + kvh*HD + c4;
            const float* vsrc = V + (size_t)(tokK + row) * (NKV*HD) + kvh*HD + c4;
            uint32_t off = (row * TPITCH + c4) * 4;
            asm volatile("cp.async.cg.shared.global [%0], [%1], 16;" :: "r"(kdst + off), "l"(ksrc));
            asm volatile("cp.async.cg.shared.global [%0], [%1], 16;" :: "r"(vdst + off), "l"(vsrc));
        }
        asm volatile("cp.async.commit_group;" ::: "memory");
    };
    loadKV(0);    // commits group containing Q + KV0

    float m0 = -1e30f, m1 = -1e30f, l0 = 0.f, l1 = 0.f;
    float o[8][4];
#pragma unroll
    for (int di = 0; di < 8; di++)
#pragma unroll
        for (int t = 0; t < 4; t++) o[di][t] = 0.f;

    for (int kt = 0; kt <= qt; kt++) {
        int buf = kt & 1;
        if (kt < qt) loadKV(kt + 1);
        if (kt < qt) asm volatile("cp.async.wait_group 1;" ::: "memory");
        else         asm volatile("cp.async.wait_group 0;" ::: "memory");
        __syncthreads();

        // ---- S = Q @ K^T ----
        float s[8][4];
#pragma unroll
        for (int ni = 0; ni < 8; ni++)
#pragma unroll
            for (int t = 0; t < 4; t++) s[ni][t] = 0.f;

        const float* ks = sm + (1 + buf) * TFLOAT;
#pragma unroll
        for (int kd = 0; kd < 8; kd++) {
            uint32_t af[4];
            const float* qb = Qs + rloc * TPITCH + kd*8 + (lane & 3);
            af[0] = fb(qb[0]);            af[1] = fb(qb[8*TPITCH]);
            af[2] = fb(qb[4]);            af[3] = fb(qb[8*TPITCH + 4]);
#pragma unroll
            for (int ni = 0; ni < 8; ni++) {
                const float* kb = ks + (ni*8 + (lane >> 2)) * TPITCH + kd*8 + (lane & 3);
                uint32_t bf[2] = { fb(kb[0]), fb(kb[4]) };
                mma8(s[ni], af, bf);
            }
        }

        // scale + causal mask (diagonal tile only)
#pragma unroll
        for (int ni = 0; ni < 8; ni++)
#pragma unroll
            for (int t = 0; t < 4; t++) s[ni][t] *= 0.125f;
        if (kt == qt) {
#pragma unroll
            for (int ni = 0; ni < 8; ni++) {
                int c = ni*8 + 2*(lane & 3);
                if (c     > rloc)     s[ni][0] = -1e30f;
                if (c + 1 > rloc)     s[ni][1] = -1e30f;
                if (c     > rloc + 8) s[ni][2] = -1e30f;
                if (c + 1 > rloc + 8) s[ni][3] = -1e30f;
            }
        }

        // ---- online softmax (rows rloc, rloc+8; 4 lanes per row) ----
        float mx0 = -1e30f, mx1 = -1e30f;
#pragma unroll
        for (int ni = 0; ni < 8; ni++) {
            mx0 = fmaxf(mx0, fmaxf(s[ni][0], s[ni][1]));
            mx1 = fmaxf(mx1, fmaxf(s[ni][2], s[ni][3]));
        }
        mx0 = fmaxf(mx0, __shfl_xor_sync(0xffffffffu, mx0, 1));
        mx0 = fmaxf(mx0, __shfl_xor_sync(0xffffffffu, mx0, 2));
        mx1 = fmaxf(mx1, __shfl_xor_sync(0xffffffffu, mx1, 1));
        mx1 = fmaxf(mx1, __shfl_xor_sync(0xffffffffu, mx1, 2));
        float nm0 = fmaxf(m0, mx0), nm1 = fmaxf(m1, mx1);
        float a0 = __expf(m0 - nm0), a1 = __expf(m1 - nm1);
        m0 = nm0; m1 = nm1;
        float sum0 = 0.f, sum1 = 0.f;
#pragma unroll
        for (int ni = 0; ni < 8; ni++) {
            s[ni][0] = __expf(s[ni][0] - nm0);
            s[ni][1] = __expf(s[ni][1] - nm0);
            s[ni][2] = __expf(s[ni][2] - nm1);
            s[ni][3] = __expf(s[ni][3] - nm1);
            sum0 += s[ni][0] + s[ni][1];
            sum1 += s[ni][2] + s[ni][3];
        }
        sum0 += __shfl_xor_sync(0xffffffffu, sum0, 1);
        sum0 += __shfl_xor_sync(0xffffffffu, sum0, 2);
        sum1 += __shfl_xor_sync(0xffffffffu, sum1, 1);
        sum1 += __shfl_xor_sync(0xffffffffu, sum1, 2);
        l0 = l0 * a0 + sum0;
        l1 = l1 * a1 + sum1;
#pragma unroll
        for (int di = 0; di < 8; di++) {
            o[di][0] *= a0; o[di][1] *= a0;
            o[di][2] *= a1; o[di][3] *= a1;
        }

        // ---- stage P (tf32-rounded) — warp-private rows ----
#pragma unroll
        for (int ni = 0; ni < 8; ni++) {
            int c = ni*8 + 2*(lane & 3);
            *(float2*)&Ps[rloc * TPITCH + c] =
                make_float2(rn_tf32(s[ni][0]), rn_tf32(s[ni][1]));
            *(float2*)&Ps[(rloc + 8) * TPITCH + c] =
                make_float2(rn_tf32(s[ni][2]), rn_tf32(s[ni][3]));
        }
        __syncwarp();

        // ---- O += P @ V ----
        const float* vs = sm + (3 + buf) * TFLOAT;
#pragma unroll
        for (int kj = 0; kj < 8; kj++) {
            uint32_t af[4];
            const float* pb = Ps + rloc * TPITCH + kj*8 + (lane & 3);
            af[0] = fb(pb[0]);            af[1] = fb(pb[8*TPITCH]);
            af[2] = fb(pb[4]);            af[3] = fb(pb[8*TPITCH + 4]);
#pragma unroll
            for (int di = 0; di < 8; di++) {
                const float* vb = vs + (kj*8 + (lane & 3)) * TPITCH + di*8 + (lane >> 2);
                uint32_t bf[2] = { fb(vb[0]), fb(vb[4*TPITCH]) };
                mma8(o[di], af, bf);
            }
        }
        __syncthreads();   // protect buffers before next iteration's loads
    }

    // epilogue: normalize, round to tf32 (input of O-proj mma)
    float i0 = 1.0f / l0, i1 = 1.0f / l1;
    int gr = tokQ + rloc;
#pragma unroll
    for (int di = 0; di < 8; di++) {
        int c = di*8 + 2*(lane & 3);
        *(float2*)&O[(size_t)gr * (NH*HD) + h*HD + c] =
            make_float2(rn_tf32(o[di][0] * i0), rn_tf32(o[di][1] * i0));
        *(float2*)&O[(size_t)(gr + 8) * (NH*HD) + h*HD + c] =
            make_float2(rn_tf32(o[di][2] * i1), rn_tf32(o[di][3] * i1));
    }
}

// ---------------- launch ----------------------------------------------------
extern "C" void kernel_launch(void* const* d_in, const int* in_sizes, int n_in,
                              void* d_out, int out_size) {
    const float* X  = (const float*)d_in[0];
    // d_in[1] = attention_mask: fixed causal mask -> implemented analytically
    const float* Wq = (const float*)d_in[2];
    const float* bq = (const float*)d_in[3];
    const float* Wk = (const float*)d_in[4];
    const float* bk = (const float*)d_in[5];
    const float* Wv = (const float*)d_in[6];
    const float* bv = (const float*)d_in[7];
    const float* Wo = (const float*)d_in[8];
    float* out = (float*)d_out;

    float *q, *k, *v, *att, *zb, *xr, *wq, *wk, *wv, *wo;
    cudaGetSymbolAddress((void**)&q,   g_q);
    cudaGetSymbolAddress((void**)&k,   g_k);
    cudaGetSymbolAddress((void**)&v,   g_v);
    cudaGetSymbolAddress((void**)&att, g_att);
    cudaGetSymbolAddress((void**)&zb,  g_zero);
    cudaGetSymbolAddress((void**)&xr,  g_xr);
    cudaGetSymbolAddress((void**)&wq,  g_wq);
    cudaGetSymbolAddress((void**)&wk,  g_wk);
    cudaGetSymbolAddress((void**)&wv,  g_wv);
    cudaGetSymbolAddress((void**)&wo,  g_wo);

    // tf32 pre-rounding (once)
    copy_rn_kernel<<<(NTOK*HID + 255)/256, 256>>>(X,  xr, NTOK*HID);
    copy_rn_kernel<<<(HID*NH*HD + 255)/256, 256>>>(Wq, wq, HID*NH*HD);
    copy_rn_kernel<<<(HID*NKV*HD + 255)/256, 256>>>(Wk, wk, HID*NKV*HD);
    copy_rn_kernel<<<(HID*NKV*HD + 255)/256, 256>>>(Wv, wv, HID*NKV*HD);
    copy_rn_kernel<<<(HID*HID + 255)/256, 256>>>(Wo, wo, HID*HID);

    // fused QKV projection (tf32 mma)
    gemm_qkv_kernel<<<dim3(9, NTOK/128), 256>>>(xr, wq, wk, wv, bq, bk, bv, q, k, v);

    // RoPE (rounds q,k to tf32)
    int nrope = NTOK*NH*32 + NTOK*NKV*32;
    rope_kernel<<<(nrope + 255) / 256, 256>>>(q, k);

    // attention (tf32 mma flash)
    cudaFuncSetAttribute(attn_kernel, cudaFuncAttributeMaxDynamicSharedMemorySize, ATT_SMEM);
    attn_kernel<<<dim3(SEQ/64, BATCH*NH), 128, ATT_SMEM>>>(q, k, v, att);

    // output projection (tf32 mma)
    gemm_o_kernel<<<dim3(HID/128, NTOK/128), 256>>>(att, wo, zb, out);
}

// round 5
// speedup vs baseline: 5.5710x; 2.1109x over previous
#include <cuda_runtime.h>
#include <cuda_fp16.h>
#include <math.h>
#include <stdint.h>

#define SEQ   2048
#define BATCH 2
#define NTOK  4096
#define HID   896
#define NH    14
#define NKV   2
#define HD    64
#define NGRP  7
#define KD    896            // inner dim for all projections (NH*HD == HID)
#define KITERS (KD/32)       // 28

// ---------------- scratch (allocation-free rule) ----------------------------
__device__ __half g_xh [NTOK*HID];
__device__ __half g_q  [NTOK*NH*HD];
__device__ __half g_k  [NTOK*NKV*HD];
__device__ __half g_v  [NTOK*NKV*HD];
__device__ __half g_att[NTOK*NH*HD];
__device__ __half g_wq [NH*HD*HID];    // W^T  [N][K]  fp16
__device__ __half g_wk [NKV*HD*HID];
__device__ __half g_wv [NKV*HD*HID];
__device__ __half g_wo [HID*HID];
__device__ float  g_zero[HID];         // zeros

// ---------------- helpers ---------------------------------------------------
__device__ __forceinline__ uint32_t cvta_smem(const void* p) {
    uint32_t a;
    asm("{ .reg .u64 t; cvta.to.shared.u64 t, %1; cvt.u32.u64 %0, t; }"
        : "=r"(a) : "l"(p));
    return a;
}
__device__ __forceinline__ void ldsm4(uint32_t* r, uint32_t addr) {
    asm volatile("ldmatrix.sync.aligned.m8n8.x4.shared.b16 {%0,%1,%2,%3}, [%4];"
        : "=r"(r[0]), "=r"(r[1]), "=r"(r[2]), "=r"(r[3]) : "r"(addr));
}
__device__ __forceinline__ void ldsm4t(uint32_t* r, uint32_t addr) {
    asm volatile("ldmatrix.sync.aligned.m8n8.x4.trans.shared.b16 {%0,%1,%2,%3}, [%4];"
        : "=r"(r[0]), "=r"(r[1]), "=r"(r[2]), "=r"(r[3]) : "r"(addr));
}
// C(16x8,f32) += A(16x16,f16) * B(16x8,f16)
__device__ __forceinline__ void mma16(float* c, const uint32_t* a, const uint32_t* b) {
    asm volatile("mma.sync.aligned.m16n8k16.row.col.f32.f16.f16.f32 "
        "{%0,%1,%2,%3}, {%4,%5,%6,%7}, {%8,%9}, {%0,%1,%2,%3};"
        : "+f"(c[0]), "+f"(c[1]), "+f"(c[2]), "+f"(c[3])
        : "r"(a[0]), "r"(a[1]), "r"(a[2]), "r"(a[3]), "r"(b[0]), "r"(b[1]));
}

// ---------------- prep kernels ----------------------------------------------
__global__ void conv_x_kernel(const float* __restrict__ src, __half* __restrict__ dst, int n) {
    int i = blockIdx.x * blockDim.x + threadIdx.x;
    if (i < n) dst[i] = __float2half_rn(src[i]);
}
// Wt[n][k] = half(W[k][n]);  W [K,N] fp32 -> Wt [N,K] fp16
__global__ void conv_wT_kernel(const float* __restrict__ W, __half* __restrict__ Wt,
                               int K, int N) {
    __shared__ float t[32][33];
    int k0 = blockIdx.x * 32, n0 = blockIdx.y * 32;
    int tx = threadIdx.x, ty = threadIdx.y;   // 32 x 8
#pragma unroll
    for (int i = ty; i < 32; i += 8) t[i][tx] = W[(size_t)(k0 + i) * N + n0 + tx];
    __syncthreads();
#pragma unroll
    for (int i = ty; i < 32; i += 8)
        Wt[(size_t)(n0 + i) * K + k0 + tx] = __float2half_rn(t[tx][i]);
}

// ---------------- fp16 mma GEMM body ----------------------------------------
// C[M,N] = A[M,KD]h @ Wt[N,KD]h^T + bias.  CTA 128x128, 256 thr / 8 warps,
// warp tile 32x64 (mi=2, ni=8).  BK=32, double-buffered cp.async, ldmatrix.
#define GP 40   // smem pitch in halves (80B = 5 chunks -> conflict-free ldmatrix)

__device__ __forceinline__ void gemm_body_h(
    const __half* __restrict__ A, const __half* __restrict__ Wt,
    const float* __restrict__ bias,
    __half* __restrict__ Ch, float* __restrict__ Cf,
    int N, int colBase)
{
    __shared__ __half As[2][128*GP];
    __shared__ __half Bs[2][128*GP];

    const int tid  = threadIdx.x;
    const int lane = tid & 31, wid = tid >> 5;
    const int wrow = (wid >> 1) * 32, wcol = (wid & 1) * 64;
    const int rowBase = blockIdx.y * 128;
    const int m4 = lane >> 3, l7 = lane & 7;

    uint32_t sA[2] = { cvta_smem(As[0]), cvta_smem(As[1]) };
    uint32_t sB[2] = { cvta_smem(Bs[0]), cvta_smem(Bs[1]) };

    auto load = [&](int it) {
        int buf = it & 1, k0 = it * 32;
#pragma unroll
        for (int p = 0; p < 2; p++) {
            int id = tid + p * 256;
            int row = id >> 2, c = id & 3;
            const __half* srcA = A  + (size_t)(rowBase + row) * KD + k0 + c * 8;
            const __half* srcB = Wt + (size_t)(colBase + row) * KD + k0 + c * 8;
            uint32_t off = (row * GP + c * 8) * 2;
            asm volatile("cp.async.cg.shared.global [%0], [%1], 16;" :: "r"(sA[buf] + off), "l"(srcA));
            asm volatile("cp.async.cg.shared.global [%0], [%1], 16;" :: "r"(sB[buf] + off), "l"(srcB));
        }
        asm volatile("cp.async.commit_group;" ::: "memory");
    };

    float acc[2][8][4];
#pragma unroll
    for (int mi = 0; mi < 2; mi++)
#pragma unroll
        for (int ni = 0; ni < 8; ni++)
#pragma unroll
            for (int t = 0; t < 4; t++) acc[mi][ni][t] = 0.f;

    load(0); load(1);

    for (int it = 0; it < KITERS; it++) {
        int buf = it & 1;
        if (it < KITERS - 1) asm volatile("cp.async.wait_group 1;" ::: "memory");
        else                 asm volatile("cp.async.wait_group 0;" ::: "memory");
        __syncthreads();

#pragma unroll
        for (int ks = 0; ks < 2; ks++) {
            uint32_t a[2][4];
#pragma unroll
            for (int mi = 0; mi < 2; mi++)
                ldsm4(a[mi], sA[buf] +
                    ((wrow + mi*16 + (m4 & 1)*8 + l7) * GP + (ks*2 + (m4 >> 1)) * 8) * 2);
#pragma unroll
            for (int p = 0; p < 4; p++) {
                uint32_t b[4];
                ldsm4(b, sB[buf] +
                    ((wcol + p*16 + (m4 >> 1)*8 + l7) * GP + (ks*2 + (m4 & 1)) * 8) * 2);
                mma16(acc[0][2*p],   a[0], b);
                mma16(acc[0][2*p+1], a[0], b + 2);
                mma16(acc[1][2*p],   a[1], b);
                mma16(acc[1][2*p+1], a[1], b + 2);
            }
        }
        __syncthreads();
        if (it + 2 < KITERS) load(it + 2);
    }

#pragma unroll
    for (int mi = 0; mi < 2; mi++) {
        int r0 = rowBase + wrow + mi*16 + (lane >> 2);
#pragma unroll
        for (int ni = 0; ni < 8; ni++) {
            int c = colBase + wcol + ni*8 + 2*(lane & 3);
            float v0 = acc[mi][ni][0] + bias[c];
            float v1 = acc[mi][ni][1] + bias[c+1];
            float v2 = acc[mi][ni][2] + bias[c];
            float v3 = acc[mi][ni][3] + bias[c+1];
            if (Ch) {
                *(__half2*)&Ch[(size_t)r0 * N + c]       = __floats2half2_rn(v0, v1);
                *(__half2*)&Ch[(size_t)(r0+8) * N + c]   = __floats2half2_rn(v2, v3);
            } else {
                *(float2*)&Cf[(size_t)r0 * N + c]     = make_float2(v0, v1);
                *(float2*)&Cf[(size_t)(r0+8) * N + c] = make_float2(v2, v3);
            }
        }
    }
}

// fused QKV: bx 0..6 -> Wq col tiles, 7 -> Wk, 8 -> Wv
__global__ void __launch_bounds__(256) gemm_qkv_kernel(
    const __half* __restrict__ X,
    const __half* __restrict__ wq, const __half* __restrict__ wk, const __half* __restrict__ wv,
    const float* __restrict__ bq, const float* __restrict__ bk, const float* __restrict__ bv,
    __half* __restrict__ q, __half* __restrict__ k, __half* __restrict__ v)
{
    int bx = blockIdx.x;
    if (bx < 7)       gemm_body_h(X, wq, bq, q, nullptr, NH*HD,  bx*128);
    else if (bx == 7) gemm_body_h(X, wk, bk, k, nullptr, NKV*HD, 0);
    else              gemm_body_h(X, wv, bv, v, nullptr, NKV*HD, 0);
}

__global__ void __launch_bounds__(256) gemm_o_kernel(
    const __half* __restrict__ A, const __half* __restrict__ W,
    const float* __restrict__ bias, float* __restrict__ C)
{
    gemm_body_h(A, W, bias, nullptr, C, HID, blockIdx.x * 128);
}

// ---------------- RoPE (fp16 in-place; q gets 1/8 folded in) ----------------
__global__ void rope_kernel(__half* __restrict__ q, __half* __restrict__ k) {
    const int nq = NTOK * NH * 32;
    const int nk = NTOK * NKV * 32;
    int idx = blockIdx.x * blockDim.x + threadIdx.x;
    if (idx >= nq + nk) return;

    __half* buf; int tok, off, d; float scale;
    if (idx < nq) {
        d = idx & 31;
        int r = idx >> 5;
        int h = r % NH; tok = r / NH;
        buf = q; off = tok * NH * HD + h * HD; scale = 0.125f;
    } else {
        int r2 = idx - nq;
        d = r2 & 31;
        int r = r2 >> 5;
        int h = r & 1; tok = r >> 1;
        buf = k; off = tok * NKV * HD + h * HD; scale = 1.0f;
    }
    int s = tok & (SEQ - 1);
    float inv = powf(1.0e6f, -((float)d) * (1.0f / 32.0f));
    float ang = (float)s * inv;
    float c = cosf(ang), sn = sinf(ang);
    float x1 = __half2float(buf[off + d]);
    float x2 = __half2float(buf[off + d + 32]);
    buf[off + d]      = __float2half_rn((x1 * c - x2 * sn) * scale);
    buf[off + d + 32] = __float2half_rn((x2 * c + x1 * sn) * scale);
}

// ---------------- flash attention, fp16 mma + ldmatrix ----------------------
// 64q x 64k tile, 128 thr / 4 warps, warp = 16 rows x 64 cols (softmax warp-local).
#define AP 72                 // pitch in halves (144B = 9 chunks -> conflict-free)
#define ATILE (64*AP)         // halves per tile
#define ATT_SMEM (6*ATILE*2)  // Q, K0, K1, V0, V1, P  = 55296 B

__global__ void __launch_bounds__(128) attn_kernel(
    const __half* __restrict__ Q, const __half* __restrict__ K,
    const __half* __restrict__ V, __half* __restrict__ O)
{
    extern __shared__ __half sh[];
    uint32_t smb = cvta_smem(sh);

    const int qt  = blockIdx.x;
    const int bh  = blockIdx.y;
    const int b   = bh / NH, h = bh % NH, kvh = h / NGRP;
    const int tid = threadIdx.x;
    const int lane = tid & 31, wid = tid >> 5;
    const int rw = wid * 16;
    const int rloc = rw + (lane >> 2);
    const int m4 = lane >> 3, l7 = lane & 7;
    const int tokQ = b * SEQ + qt * 64;

    // Q tile: 64 rows x 8 chunks
#pragma unroll
    for (int p = 0; p < 4; p++) {
        int id = tid + p * 128;
        int row = id >> 3, c = id & 7;
        const __half* src = Q + (size_t)(tokQ + row) * (NH*HD) + h*HD + c*8;
        asm volatile("cp.async.cg.shared.global [%0], [%1], 16;"
                     :: "r"(smb + (row * AP + c*8) * 2), "l"(src));
    }
    auto loadKV = [&](int kt) {
        int buf = kt & 1;
        int tokK = b * SEQ + kt * 64;
        uint32_t kb = smb + (1 + buf) * ATILE * 2;
        uint32_t vb = smb + (3 + buf) * ATILE * 2;
#pragma unroll
        for (int p = 0; p < 4; p++) {
            int id = tid + p * 128;
            int row = id >> 3, c = id & 7;
            const __half* ks = K + (size_t)(tokK + row) * (NKV*HD) + kvh*HD + c*8;
            const __half* vs = V + (size_t)(tokK + row) * (NKV*HD) + kvh*HD + c*8;
            uint32_t off = (row * AP + c*8) * 2;
            asm volatile("cp.async.cg.shared.global [%0], [%1], 16;" :: "r"(kb + off), "l"(ks));
            asm volatile("cp.async.cg.shared.global [%0], [%1], 16;" :: "r"(vb + off), "l"(vs));
        }
        asm volatile("cp.async.commit_group;" ::: "memory");
    };
    loadKV(0);

    float m0 = -1e30f, m1 = -1e30f, l0 = 0.f, l1 = 0.f;
    float o[8][4];
#pragma unroll
    for (int di = 0; di < 8; di++)
#pragma unroll
        for (int t = 0; t < 4; t++) o[di][t] = 0.f;

    const uint32_t pbase = smb + 5 * ATILE * 2;

    for (int kt = 0; kt <= qt; kt++) {
        int buf = kt & 1;
        if (kt < qt) loadKV(kt + 1);
        if (kt < qt) asm volatile("cp.async.wait_group 1;" ::: "memory");
        else         asm volatile("cp.async.wait_group 0;" ::: "memory");
        __syncthreads();

        const uint32_t kbase = smb + (1 + buf) * ATILE * 2;
        const uint32_t vbase = smb + (3 + buf) * ATILE * 2;

        // ---- S = Q @ K^T (scale pre-folded into Q) ----
        float s[8][4];
#pragma unroll
        for (int ni = 0; ni < 8; ni++)
#pragma unroll
            for (int t = 0; t < 4; t++) s[ni][t] = 0.f;
#pragma unroll
        for (int ks = 0; ks < 4; ks++) {
            uint32_t a[4];
            ldsm4(a, smb + ((rw + (m4 & 1)*8 + l7) * AP + (ks*2 + (m4 >> 1)) * 8) * 2);
#pragma unroll
            for (int p = 0; p < 4; p++) {
                uint32_t bf[4];
                ldsm4(bf, kbase + ((p*16 + (m4 >> 1)*8 + l7) * AP + (ks*2 + (m4 & 1)) * 8) * 2);
                mma16(s[2*p],   a, bf);
                mma16(s[2*p+1], a, bf + 2);
            }
        }

        // causal mask on diagonal tile
        if (kt == qt) {
#pragma unroll
            for (int ni = 0; ni < 8; ni++) {
                int c = ni*8 + 2*(lane & 3);
                if (c     > rloc)     s[ni][0] = -1e30f;
                if (c + 1 > rloc)     s[ni][1] = -1e30f;
                if (c     > rloc + 8) s[ni][2] = -1e30f;
                if (c + 1 > rloc + 8) s[ni][3] = -1e30f;
            }
        }

        // ---- online softmax (rows rloc, rloc+8; 4 lanes/row) ----
        float mx0 = -1e30f, mx1 = -1e30f;
#pragma unroll
        for (int ni = 0; ni < 8; ni++) {
            mx0 = fmaxf(mx0, fmaxf(s[ni][0], s[ni][1]));
            mx1 = fmaxf(mx1, fmaxf(s[ni][2], s[ni][3]));
        }
        mx0 = fmaxf(mx0, __shfl_xor_sync(0xffffffffu, mx0, 1));
        mx0 = fmaxf(mx0, __shfl_xor_sync(0xffffffffu, mx0, 2));
        mx1 = fmaxf(mx1, __shfl_xor_sync(0xffffffffu, mx1, 1));
        mx1 = fmaxf(mx1, __shfl_xor_sync(0xffffffffu, mx1, 2));
        float nm0 = fmaxf(m0, mx0), nm1 = fmaxf(m1, mx1);
        float a0 = __expf(m0 - nm0), a1 = __expf(m1 - nm1);
        m0 = nm0; m1 = nm1;
        float sum0 = 0.f, sum1 = 0.f;
#pragma unroll
        for (int ni = 0; ni < 8; ni++) {
            s[ni][0] = __expf(s[ni][0] - nm0);
            s[ni][1] = __expf(s[ni][1] - nm0);
            s[ni][2] = __expf(s[ni][2] - nm1);
            s[ni][3] = __expf(s[ni][3] - nm1);
            sum0 += s[ni][0] + s[ni][1];
            sum1 += s[ni][2] + s[ni][3];
        }
        sum0 += __shfl_xor_sync(0xffffffffu, sum0, 1);
        sum0 += __shfl_xor_sync(0xffffffffu, sum0, 2);
        sum1 += __shfl_xor_sync(0xffffffffu, sum1, 1);
        sum1 += __shfl_xor_sync(0xffffffffu, sum1, 2);
        l0 = l0 * a0 + sum0;
        l1 = l1 * a1 + sum1;
#pragma unroll
        for (int di = 0; di < 8; di++) {
            o[di][0] *= a0; o[di][1] *= a0;
            o[di][2] *= a1; o[di][3] *= a1;
        }

        // ---- stage P as fp16 (warp-private rows) ----
        {
            __half* Ps = sh + 5 * ATILE;
#pragma unroll
            for (int ni = 0; ni < 8; ni++) {
                int c = ni*8 + 2*(lane & 3);
                *(__half2*)&Ps[rloc * AP + c]       = __floats2half2_rn(s[ni][0], s[ni][1]);
                *(__half2*)&Ps[(rloc + 8) * AP + c] = __floats2half2_rn(s[ni][2], s[ni][3]);
            }
        }
        __syncwarp();

        // ---- O += P @ V  (V fragments via ldmatrix.trans) ----
#pragma unroll
        for (int ks = 0; ks < 4; ks++) {
            uint32_t a[4];
            ldsm4(a, pbase + ((rw + (m4 & 1)*8 + l7) * AP + (ks*2 + (m4 >> 1)) * 8) * 2);
#pragma unroll
            for (int p = 0; p < 4; p++) {
                uint32_t bf[4];
                ldsm4t(bf, vbase + ((ks*16 + (m4 & 1)*8 + l7) * AP + (p*2 + (m4 >> 1)) * 8) * 2);
                mma16(o[2*p],   a, bf);
                mma16(o[2*p+1], a, bf + 2);
            }
        }
        __syncthreads();   // protect K/V/P buffers before next loads
    }

    // epilogue: normalize, store fp16 (input of O-proj)
    float i0 = 1.0f / l0, i1 = 1.0f / l1;
    int gr = tokQ + rloc;
#pragma unroll
    for (int di = 0; di < 8; di++) {
        int c = di*8 + 2*(lane & 3);
        *(__half2*)&O[(size_t)gr * (NH*HD) + h*HD + c] =
            __floats2half2_rn(o[di][0] * i0, o[di][1] * i0);
        *(__half2*)&O[(size_t)(gr + 8) * (NH*HD) + h*HD + c] =
            __floats2half2_rn(o[di][2] * i1, o[di][3] * i1);
    }
}

// ---------------- launch ----------------------------------------------------
extern "C" void kernel_launch(void* const* d_in, const int* in_sizes, int n_in,
                              void* d_out, int out_size) {
    const float* X  = (const float*)d_in[0];
    // d_in[1] = attention_mask: fixed causal mask -> analytic
    const float* Wq = (const float*)d_in[2];
    const float* bq = (const float*)d_in[3];
    const float* Wk = (const float*)d_in[4];
    const float* bk = (const float*)d_in[5];
    const float* Wv = (const float*)d_in[6];
    const float* bv = (const float*)d_in[7];
    const float* Wo = (const float*)d_in[8];
    float* out = (float*)d_out;

    __half *xh, *q, *k, *v, *att, *wq, *wk, *wv, *wo;
    float *zb;
    cudaGetSymbolAddress((void**)&xh,  g_xh);
    cudaGetSymbolAddress((void**)&q,   g_q);
    cudaGetSymbolAddress((void**)&k,   g_k);
    cudaGetSymbolAddress((void**)&v,   g_v);
    cudaGetSymbolAddress((void**)&att, g_att);
    cudaGetSymbolAddress((void**)&wq,  g_wq);
    cudaGetSymbolAddress((void**)&wk,  g_wk);
    cudaGetSymbolAddress((void**)&wv,  g_wv);
    cudaGetSymbolAddress((void**)&wo,  g_wo);
    cudaGetSymbolAddress((void**)&zb,  g_zero);

    // prep: fp32 -> fp16 (X straight copy; weights transposed to [N][K])
    conv_x_kernel<<<(NTOK*HID + 255)/256, 256>>>(X, xh, NTOK*HID);
    conv_wT_kernel<<<dim3(KD/32, (NH*HD)/32),  dim3(32,8)>>>(Wq, wq, KD, NH*HD);
    conv_wT_kernel<<<dim3(KD/32, (NKV*HD)/32), dim3(32,8)>>>(Wk, wk, KD, NKV*HD);
    conv_wT_kernel<<<dim3(KD/32, (NKV*HD)/32), dim3(32,8)>>>(Wv, wv, KD, NKV*HD);
    conv_wT_kernel<<<dim3(KD/32, HID/32),      dim3(32,8)>>>(Wo, wo, KD, HID);

    // fused QKV projection (fp16 HMMA)
    gemm_qkv_kernel<<<dim3(9, NTOK/128), 256>>>(xh, wq, wk, wv, bq, bk, bv, q, k, v);

    // RoPE (folds 1/8 into q)
    int nrope = NTOK*NH*32 + NTOK*NKV*32;
    rope_kernel<<<(nrope + 255) / 256, 256>>>(q, k);

    // attention
    cudaFuncSetAttribute(attn_kernel, cudaFuncAttributeMaxDynamicSharedMemorySize, ATT_SMEM);
    attn_kernel<<<dim3(SEQ/64, BATCH*NH), 128, ATT_SMEM>>>(q, k, v, att);

    // output projection (fp32 out)
    gemm_o_kernel<<<dim3(HID/128, NTOK/128), 256>>>(att, wo, zb, out);
}